// round 7
// baseline (speedup 1.0000x reference)
#include <cuda_runtime.h>
#include <cuda_fp16.h>
#include <cstdint>

#define NB 12
#define DM 128
#define NH 2
#define HD 64
#define SETUP_BLOCKS 312
#define P2_BLOCKS 2

struct Consts {
    float ta[NH];
    float u[NH];
    float bo;
    float pad[3];
    float tb[NH][NB];
    float gam[NH][NB];
    float w[NH][NB];
    float del[NH][NB][NB];
};

__device__ __align__(16) Consts g_c;
__device__ float g_av[3][DM];
__device__ float g_cv[3][NB][DM];
__device__ int g_cnt1, g_cnt2, g_fin;

__device__ __forceinline__ __half2 h2ex2(__half2 v) {
    uint32_t a = *reinterpret_cast<uint32_t*>(&v), b;
    asm("ex2.approx.f16x2 %0, %1;" : "=r"(b) : "r"(a));
    return *reinterpret_cast<__half2*>(&b);
}
__device__ __forceinline__ int ld_acq(const int* p) {
    int v;
    asm volatile("ld.acquire.gpu.b32 %0, [%1];" : "=r"(v) : "l"(p) : "memory");
    return v;
}
__device__ __forceinline__ float warp_sum(float v) {
    v += __shfl_xor_sync(0xffffffffu, v, 16);
    v += __shfl_xor_sync(0xffffffffu, v, 8);
    v += __shfl_xor_sync(0xffffffffu, v, 4);
    v += __shfl_xor_sync(0xffffffffu, v, 2);
    v += __shfl_xor_sync(0xffffffffu, v, 1);
    return v;
}

// ---------------------------------------------------------------------------
// Single fused kernel. All blocks co-resident (512 blocks <= 148*4 slots).
// ---------------------------------------------------------------------------
__global__ void __launch_bounds__(256, 4) spec_fused(
        const float* __restrict__ x, float* __restrict__ out, int N2,
        const float* __restrict__ we, const float* __restrict__ be,
        const float* __restrict__ bp,
        const float* __restrict__ Wq, const float* __restrict__ bq,
        const float* __restrict__ Wk, const float* __restrict__ bk,
        const float* __restrict__ Wv, const float* __restrict__ bv,
        const float* __restrict__ Wo, const float* __restrict__ bo) {
    const int tid = threadIdx.x;
    const int bid = blockIdx.x;
    const int lane = tid & 31;

    // ---------------- phase 1: blocks 0..311, 2 warp-dots per warp ----------
    if (bid < SETUP_BLOCKS) {
        int gw = bid * 8 + (tid >> 5);     // 0..2495
        int d0 = gw * 2;                   // even dot index
        int m = d0 / (13 * DM);
        int r = d0 - m * 13 * DM;
        int v = r >> 7;
        int i = r & 127;                   // even, i+1 in same v block
        const float* W  = (m == 0) ? Wq : (m == 1) ? Wk : Wv;
        const float* bb = (m == 0) ? bq : (m == 1) ? bk : bv;

        float4 r0 = ((const float4*)(W + i * DM))[lane];
        float4 r1 = ((const float4*)(W + (i + 1) * DM))[lane];
        float4 ev;
        if (v == 0) {
            ev = ((const float4*)we)[lane];
        } else {
            float4 e = ((const float4*)be)[lane];
            float4 p = ((const float4*)(bp + (v - 1) * DM))[lane];
            ev = make_float4(e.x + p.x, e.y + p.y, e.z + p.z, e.w + p.w);
        }
        float p0 = r0.x * ev.x + r0.y * ev.y + r0.z * ev.z + r0.w * ev.w;
        float p1 = r1.x * ev.x + r1.y * ev.y + r1.z * ev.z + r1.w * ev.w;
        p0 = warp_sum(p0);
        p1 = warp_sum(p1);
        if (lane == 0) {
            if (v == 0) {
                g_av[m][i] = p0; g_av[m][i + 1] = p1;
            } else {
                g_cv[m][v - 1][i]     = p0 + bb[i];
                g_cv[m][v - 1][i + 1] = p1 + bb[i + 1];
            }
        }
        __threadfence();
        __syncthreads();
        if (tid == 0) atomicAdd(&g_cnt1, 1);
    }

    // ---------------- prefetch x while setup settles ------------------------
    int t = bid * 256 + tid;
    bool valid = (t < N2);
    int n = t >> 1;
    int h = t & 1;
    float xv[NB];
    if (valid) {
        const float4* xp = (const float4*)(x + (size_t)n * NB);
        float4 a0 = xp[0], a1 = xp[1], a2 = xp[2];
        xv[0] = a0.x; xv[1] = a0.y; xv[2]  = a0.z; xv[3]  = a0.w;
        xv[4] = a1.x; xv[5] = a1.y; xv[6]  = a1.z; xv[7]  = a1.w;
        xv[8] = a2.x; xv[9] = a2.y; xv[10] = a2.z; xv[11] = a2.w;
    } else {
        #pragma unroll
        for (int q = 0; q < NB; q++) xv[q] = 0.f;
    }

    // ---------------- phase 2: blocks 0..1, one dot-64 per thread -----------
    if (bid < P2_BLOCKS) {
        while (ld_acq(&g_cnt1) < SETUP_BLOCKS) __nanosleep(64);
        __syncthreads();

        int idx = bid * 256 + tid;
        if (idx <= NH * 182) {
            const float cfac = 0.125f * 1.4426950408889634f;
            if (idx == NH * 182) {
                g_c.bo = bo[0];
            } else {
                int hh = idx / 182;
                int rr = idx % 182;
                int off = hh * HD;
                const float* a; const float* b; float* dst; float sc = cfac;
                if (rr == 0)      { a = &g_av[0][off]; b = &g_av[1][off]; dst = &g_c.ta[hh]; }
                else if (rr == 1) { a = &g_av[2][off]; b = Wo + off; dst = &g_c.u[hh]; sc = 1.0f; }
                else if (rr < 14) { int bd = rr - 2;  a = &g_av[0][off]; b = &g_cv[1][bd][off]; dst = &g_c.tb[hh][bd]; }
                else if (rr < 26) { int bd = rr - 14; a = &g_cv[0][bd][off]; b = &g_av[1][off]; dst = &g_c.gam[hh][bd]; }
                else if (rr < 38) { int bd = rr - 26; a = &g_cv[2][bd][off]; b = Wo + off; dst = &g_c.w[hh][bd]; sc = 1.0f; }
                else {
                    int id2 = rr - 38, q = id2 / NB, k = id2 % NB;
                    a = &g_cv[0][q][off]; b = &g_cv[1][k][off]; dst = &g_c.del[hh][q][k];
                }
                const float4* A = (const float4*)a;
                const float4* B = (const float4*)b;
                float acc = 0.f;
                #pragma unroll 4
                for (int j = 0; j < HD / 4; j++) {
                    float4 av = A[j], bv = B[j];
                    acc += av.x * bv.x + av.y * bv.y + av.z * bv.z + av.w * bv.w;
                }
                *dst = acc * sc;
            }
        }
        __threadfence();
        __syncthreads();
        if (tid == 0) atomicAdd(&g_cnt2, 1);
    }

    // ---------------- wait for consts ready ---------------------------------
    while (ld_acq(&g_cnt2) < P2_BLOCKS) __nanosleep(64);
    __syncthreads();

    // ---------------- load + convert consts to smem (half2) -----------------
    __shared__ __half2 sDel[NH][NB][8];
    __shared__ __half2 sTb[NH][6], sW[NH][6];
    __shared__ __half2 sGam[NH][NB];
    __shared__ __half2 sTa[NH], sU[NH];
    __shared__ float sBo;
    {
        for (int i = tid; i < NH * NB * 6; i += 256) {
            int hh = i / (NB * 6);
            int r = i % (NB * 6);
            int q = r / 6, j = r % 6;
            sDel[hh][q][j] = __floats2half2_rn(g_c.del[hh][q][2 * j],
                                               g_c.del[hh][q][2 * j + 1]);
        }
        if (tid < NH * 6) {
            int hh = tid / 6, j = tid % 6;
            sTb[hh][j] = __floats2half2_rn(g_c.tb[hh][2 * j], g_c.tb[hh][2 * j + 1]);
            sW[hh][j]  = __floats2half2_rn(g_c.w[hh][2 * j],  g_c.w[hh][2 * j + 1]);
        }
        if (tid < NH * NB) {
            int hh = tid / NB, q = tid % NB;
            float g = g_c.gam[hh][q];
            sGam[hh][q] = __floats2half2_rn(g, g);
        }
        if (tid < NH) {
            sTa[tid] = __floats2half2_rn(g_c.ta[tid], g_c.ta[tid]);
            sU[tid]  = __floats2half2_rn(g_c.u[tid],  g_c.u[tid]);
        }
        if (tid == 0) sBo = g_c.bo;
    }
    __syncthreads();

    // ---------------- main compute: fp16x2 over k-pairs ---------------------
    __half2 x2[6];
    #pragma unroll
    for (int j = 0; j < 6; j++) x2[j] = __floats2half2_rn(xv[2 * j], xv[2 * j + 1]);
    __half2 xq2[NB];
    #pragma unroll
    for (int j = 0; j < 6; j++) {
        xq2[2 * j]     = __low2half2(x2[j]);
        xq2[2 * j + 1] = __high2half2(x2[j]);
    }

    __half2 ah2 = sTa[h], uh2 = sU[h];
    __half2 t2[6], m2[6];
    #pragma unroll
    for (int j = 0; j < 6; j++) {
        t2[j] = __hfma2(x2[j], ah2, sTb[h][j]);
        m2[j] = __hfma2(x2[j], uh2, sW[h][j]);
    }

    float contrib[NB];
    #pragma unroll
    for (int q = 0; q < NB; q++) {
        __half2 gq2 = sGam[h][q];
        __half2 xq  = xq2[q];
        __half2 rs2 = __floats2half2_rn(0.f, 0.f);
        __half2 ds2 = rs2;
        #pragma unroll
        for (int j = 0; j < 6; j++) {
            __half2 s2 = __hfma2(xq, t2[j], __hfma2(x2[j], gq2, sDel[h][q][j]));
            __half2 e2 = h2ex2(s2);
            rs2 = __hadd2(rs2, e2);
            ds2 = __hfma2(e2, m2[j], ds2);
        }
        float2 rf = __half22float2(rs2);
        float2 df = __half22float2(ds2);
        contrib[q] = __fdividef(df.x + df.y, rf.x + rf.y);
    }

    #pragma unroll
    for (int q = 0; q < NB; q++)
        contrib[q] += __shfl_xor_sync(0xffffffffu, contrib[q], 1);

    if (valid && h == 0) {
        float b = sBo;
        float4 o0 = make_float4(xv[0] + contrib[0] + b,  xv[1] + contrib[1] + b,
                                xv[2] + contrib[2] + b,  xv[3] + contrib[3] + b);
        float4 o1 = make_float4(xv[4] + contrib[4] + b,  xv[5] + contrib[5] + b,
                                xv[6] + contrib[6] + b,  xv[7] + contrib[7] + b);
        float4 o2 = make_float4(xv[8] + contrib[8] + b,  xv[9] + contrib[9] + b,
                                xv[10] + contrib[10] + b, xv[11] + contrib[11] + b);
        float4* op = (float4*)(out + (size_t)n * NB);
        op[0] = o0; op[1] = o1; op[2] = o2;
    }

    // ---------------- replay-safe counter reset (last block out) ------------
    __syncthreads();
    if (tid == 0) {
        __threadfence();
        int f = atomicAdd(&g_fin, 1);
        if (f == (int)gridDim.x - 1) {
            g_cnt1 = 0;
            g_cnt2 = 0;
            g_fin = 0;
        }
    }
}

// ---------------------------------------------------------------------------
extern "C" void kernel_launch(void* const* d_in, const int* in_sizes, int n_in,
                              void* d_out, int out_size) {
    const float* x  = (const float*)d_in[0];
    const float* we = (const float*)d_in[1];
    const float* be = (const float*)d_in[2];
    const float* bp = (const float*)d_in[3];
    const float* Wq = (const float*)d_in[4];
    const float* bq = (const float*)d_in[5];
    const float* Wk = (const float*)d_in[6];
    const float* bk = (const float*)d_in[7];
    const float* Wv = (const float*)d_in[8];
    const float* bv = (const float*)d_in[9];
    const float* Wo = (const float*)d_in[10];
    const float* bo = (const float*)d_in[11];
    float* out = (float*)d_out;

    int N = in_sizes[0] / NB;   // 65536 tokens
    int N2 = 2 * N;
    int blocks = (N2 + 255) / 256;   // 512 for the fixed dataset
    if (blocks < SETUP_BLOCKS + 1) blocks = SETUP_BLOCKS + 1;

    spec_fused<<<blocks, 256>>>(x, out, N2, we, be, bp,
                                Wq, bq, Wk, bk, Wv, bv, Wo, bo);
}

// round 9
// speedup vs baseline: 1.1182x; 1.1182x over previous
#include <cuda_runtime.h>
#include <cuda_fp16.h>
#include <cstdint>

#define NB 12
#define DM 128
#define NH 2
#define HD 64

struct Consts {
    float ta[NH];
    float u[NH];
    float bo;
    float pad[3];
    float tb[NH][NB];
    float gam[NH][NB];
    float w[NH][NB];
    float del[NH][NB][NB];
};

// Two partial structs: g_cp[half]; every constant = g_cp[0].f + g_cp[1].f
__device__ __align__(16) Consts g_cp[2];

__device__ __forceinline__ __half2 h2ex2(__half2 v) {
    uint32_t a = *reinterpret_cast<uint32_t*>(&v), b;
    asm("ex2.approx.f16x2 %0, %1;" : "=r"(b) : "r"(a));
    return *reinterpret_cast<__half2*>(&b);
}

// ---------------------------------------------------------------------------
// Setup: 4 independent blocks = (head h, component-half g), 32 comps each.
// All-static smem: 33,792 + 6,656 + 3,328 + 4,096 + 512 = 48,384 B < 48 KB.
// Block computes C[64][13] = [Wq_h; Wk_h] (32-row halves) @ [we | be+bp[b]],
// vproj[d] = sum_i Wo[i]*Wv[i][d] over its 32 components, then all 365
// constant partials for its (h,g) slice. Zero cross-block communication.
// ---------------------------------------------------------------------------
__global__ void __launch_bounds__(256) spec_setup(
        const float* __restrict__ we, const float* __restrict__ be,
        const float* __restrict__ bp,
        const float* __restrict__ Wq, const float* __restrict__ bq,
        const float* __restrict__ Wk, const float* __restrict__ bk,
        const float* __restrict__ Wv, const float* __restrict__ bv,
        const float* __restrict__ Wo, const float* __restrict__ bo) {
    __shared__ float4 sW4[64 * 33];               // padded rows: stride 33
    __shared__ float4 sE4[13][32];                // we | ebp[12]
    __shared__ float  sC[64][13];
    __shared__ float4 sVPw[8][32];
    __shared__ float  sVP[DM];

    const int tid = threadIdx.x;
    const int h = blockIdx.x >> 1;
    const int g = blockIdx.x & 1;
    const int ibase = h * HD + g * 32;

    // ---- stage E = [we, be+bp[0..11]] ----
    for (int idx = tid; idx < 13 * 32; idx += 256) {
        int e = idx / 32, c = idx % 32;
        float4 v;
        if (e == 0) {
            v = ((const float4*)we)[c];
        } else {
            float4 b4 = ((const float4*)be)[c];
            float4 p4 = ((const float4*)bp)[(e - 1) * 32 + c];
            v = make_float4(b4.x + p4.x, b4.y + p4.y, b4.z + p4.z, b4.w + p4.w);
        }
        sE4[e][c] = v;
    }
    // ---- stage Wq/Wk row-halves (coalesced), padded stride 33 ----
    for (int idx = tid; idx < 64 * 32; idx += 256) {
        int r = idx / 32, c = idx % 32;
        const float* W = (r < 32) ? Wq : Wk;
        int il = r & 31;
        sW4[r * 33 + c] = ((const float4*)(W + (ibase + il) * DM))[c];
    }
    // ---- vproj partial per warp: rows 4*wid..4*wid+3 of Wv ----
    {
        int wid = tid >> 5, lane = tid & 31;
        float4 p = make_float4(0.f, 0.f, 0.f, 0.f);
        #pragma unroll
        for (int k = 0; k < 4; k++) {
            int il = wid * 4 + k;
            float wo = Wo[ibase + il];
            float4 v4 = ((const float4*)(Wv + (ibase + il) * DM))[lane];
            p.x = fmaf(wo, v4.x, p.x);
            p.y = fmaf(wo, v4.y, p.y);
            p.z = fmaf(wo, v4.z, p.z);
            p.w = fmaf(wo, v4.w, p.w);
        }
        sVPw[wid][lane] = p;
    }
    __syncthreads();
    if (tid < 32) {
        float4 s = make_float4(0.f, 0.f, 0.f, 0.f);
        #pragma unroll
        for (int w = 0; w < 8; w++) {
            float4 p = sVPw[w][tid];
            s.x += p.x; s.y += p.y; s.z += p.z; s.w += p.w;
        }
        ((float4*)sVP)[tid] = s;
    }

    // ---- GEMM C[64][13]: 832 full dot-128 tasks over 256 threads ----
    for (int idx = tid; idx < 64 * 13; idx += 256) {
        int r = idx % 64;
        int e = idx / 64;
        float acc = 0.f;
        #pragma unroll 8
        for (int c = 0; c < 32; c++) {
            float4 w4 = sW4[r * 33 + c];
            float4 e4 = sE4[e][c];
            acc = fmaf(w4.x, e4.x, acc);
            acc = fmaf(w4.y, e4.y, acc);
            acc = fmaf(w4.z, e4.z, acc);
            acc = fmaf(w4.w, e4.w, acc);
        }
        if (e > 0) {
            int il = r & 31;
            acc += (r < 32) ? bq[ibase + il] : bk[ibase + il];
        }
        sC[r][e] = acc;
    }
    __syncthreads();

    // ---- phase 2: 365 partial constants for (h, g) ----
    const float cfac = 0.125f * 1.4426950408889634f;  // (1/sqrt(64))*log2(e)
    const float* sEf = (const float*)sE4;              // [13][128] float view

    if (tid < 182) {
        int rr = tid;
        if (rr == 1) {                       // u = vproj . we
            float acc = 0.f;
            #pragma unroll 8
            for (int d = 0; d < DM; d++) acc = fmaf(sVP[d], sEf[d], acc);
            g_cp[g].u[h] = acc;
        } else if (rr >= 26 && rr < 38) {    // w[b] = vproj . ebp_b + bv.Wo
            int b = rr - 26;
            float acc = 0.f;
            #pragma unroll 8
            for (int d = 0; d < DM; d++)
                acc = fmaf(sVP[d], sEf[(1 + b) * DM + d], acc);
            float bw = 0.f;
            #pragma unroll 8
            for (int il = 0; il < 32; il++)
                bw = fmaf(bv[ibase + il], Wo[ibase + il], bw);
            g_cp[g].w[h][b] = acc + bw;
        } else {                             // dot-32 over component slice
            const float* A;
            const float* B;
            float* dst;
            if (rr == 0)      { A = &sC[0][0];  B = &sC[32][0]; dst = &g_cp[g].ta[h]; }
            else if (rr < 14) { int b = rr - 2;
                                A = &sC[0][0];  B = &sC[32][1 + b]; dst = &g_cp[g].tb[h][b]; }
            else if (rr < 26) { int b = rr - 14;
                                A = &sC[0][1 + b]; B = &sC[32][0]; dst = &g_cp[g].gam[h][b]; }
            else              { int idx = rr - 38, q = idx / NB, k = idx % NB;
                                A = &sC[0][1 + q]; B = &sC[32][1 + k]; dst = &g_cp[g].del[h][q][k]; }
            float acc = 0.f;
            #pragma unroll 8
            for (int il = 0; il < 32; il++)
                acc = fmaf(A[il * 13], B[il * 13], acc);
            *dst = acc * cfac;
        }
    }
    if (h == 0 && tid == 182) g_cp[g].bo = (g == 0) ? bo[0] : 0.f;
}

// ---------------------------------------------------------------------------
// Main kernel: round-6 proven core (2 threads/token, fp16x2 over k-pairs).
// Prologue sums the two partial Consts structs.
// ---------------------------------------------------------------------------
__global__ __launch_bounds__(256) void spec_main(const float* __restrict__ x,
                                                 float* __restrict__ out, int N2) {
    __shared__ __half2 sDel[NH][NB][8];
    __shared__ __half2 sTb[NH][6], sW[NH][6];
    __shared__ __half2 sGam[NH][NB];
    __shared__ __half2 sTa[NH], sU[NH];
    __shared__ float sBo;

    {
        int td = threadIdx.x;
        for (int i = td; i < NH * NB * 6; i += 256) {
            int hh = i / (NB * 6);
            int r = i % (NB * 6);
            int q = r / 6, j = r % 6;
            sDel[hh][q][j] = __floats2half2_rn(
                g_cp[0].del[hh][q][2 * j]     + g_cp[1].del[hh][q][2 * j],
                g_cp[0].del[hh][q][2 * j + 1] + g_cp[1].del[hh][q][2 * j + 1]);
        }
        if (td < NH * 6) {
            int hh = td / 6, j = td % 6;
            sTb[hh][j] = __floats2half2_rn(
                g_cp[0].tb[hh][2 * j]     + g_cp[1].tb[hh][2 * j],
                g_cp[0].tb[hh][2 * j + 1] + g_cp[1].tb[hh][2 * j + 1]);
            sW[hh][j] = __floats2half2_rn(
                g_cp[0].w[hh][2 * j]      + g_cp[1].w[hh][2 * j],
                g_cp[0].w[hh][2 * j + 1]  + g_cp[1].w[hh][2 * j + 1]);
        }
        if (td < NH * NB) {
            int hh = td / NB, q = td % NB;
            float gm = g_cp[0].gam[hh][q] + g_cp[1].gam[hh][q];
            sGam[hh][q] = __floats2half2_rn(gm, gm);
        }
        if (td < NH) {
            float ta = g_cp[0].ta[td] + g_cp[1].ta[td];
            float uu = g_cp[0].u[td]  + g_cp[1].u[td];
            sTa[td] = __floats2half2_rn(ta, ta);
            sU[td]  = __floats2half2_rn(uu, uu);
        }
        if (td == 0) sBo = g_cp[0].bo + g_cp[1].bo;
    }
    __syncthreads();

    int t = blockIdx.x * blockDim.x + threadIdx.x;
    if (t >= N2) return;
    int n = t >> 1;
    int h = t & 1;

    const float4* xp = (const float4*)(x + (size_t)n * NB);
    float4 a0 = xp[0], a1 = xp[1], a2 = xp[2];
    float xv[NB] = {a0.x, a0.y, a0.z, a0.w, a1.x, a1.y, a1.z, a1.w,
                    a2.x, a2.y, a2.z, a2.w};

    __half2 x2[6];
    #pragma unroll
    for (int j = 0; j < 6; j++) x2[j] = __floats2half2_rn(xv[2 * j], xv[2 * j + 1]);
    __half2 xq2[NB];
    #pragma unroll
    for (int j = 0; j < 6; j++) {
        xq2[2 * j]     = __low2half2(x2[j]);
        xq2[2 * j + 1] = __high2half2(x2[j]);
    }

    __half2 ah2 = sTa[h], uh2 = sU[h];
    __half2 t2[6], m2[6];
    #pragma unroll
    for (int j = 0; j < 6; j++) {
        t2[j] = __hfma2(x2[j], ah2, sTb[h][j]);
        m2[j] = __hfma2(x2[j], uh2, sW[h][j]);
    }

    float contrib[NB];
    #pragma unroll
    for (int q = 0; q < NB; q++) {
        __half2 gq2 = sGam[h][q];
        __half2 xq  = xq2[q];
        __half2 rs2 = __floats2half2_rn(0.f, 0.f);
        __half2 ds2 = rs2;
        #pragma unroll
        for (int j = 0; j < 6; j++) {
            __half2 s2 = __hfma2(xq, t2[j], __hfma2(x2[j], gq2, sDel[h][q][j]));
            __half2 e2 = h2ex2(s2);
            rs2 = __hadd2(rs2, e2);
            ds2 = __hfma2(e2, m2[j], ds2);
        }
        float2 rf = __half22float2(rs2);
        float2 df = __half22float2(ds2);
        contrib[q] = __fdividef(df.x + df.y, rf.x + rf.y);
    }

    #pragma unroll
    for (int q = 0; q < NB; q++)
        contrib[q] += __shfl_xor_sync(0xffffffffu, contrib[q], 1);

    if (h == 0) {
        float b = sBo;
        float4 o0 = make_float4(xv[0] + contrib[0] + b,  xv[1] + contrib[1] + b,
                                xv[2] + contrib[2] + b,  xv[3] + contrib[3] + b);
        float4 o1 = make_float4(xv[4] + contrib[4] + b,  xv[5] + contrib[5] + b,
                                xv[6] + contrib[6] + b,  xv[7] + contrib[7] + b);
        float4 o2 = make_float4(xv[8] + contrib[8] + b,  xv[9] + contrib[9] + b,
                                xv[10] + contrib[10] + b, xv[11] + contrib[11] + b);
        float4* op = (float4*)(out + (size_t)n * NB);
        op[0] = o0; op[1] = o1; op[2] = o2;
    }
}

// ---------------------------------------------------------------------------
extern "C" void kernel_launch(void* const* d_in, const int* in_sizes, int n_in,
                              void* d_out, int out_size) {
    const float* x  = (const float*)d_in[0];
    const float* we = (const float*)d_in[1];
    const float* be = (const float*)d_in[2];
    const float* bp = (const float*)d_in[3];
    const float* Wq = (const float*)d_in[4];
    const float* bq = (const float*)d_in[5];
    const float* Wk = (const float*)d_in[6];
    const float* bk = (const float*)d_in[7];
    const float* Wv = (const float*)d_in[8];
    const float* bv = (const float*)d_in[9];
    const float* Wo = (const float*)d_in[10];
    const float* bo = (const float*)d_in[11];
    float* out = (float*)d_out;

    int N = in_sizes[0] / NB;   // 65536 tokens
    int N2 = 2 * N;

    spec_setup<<<4, 256>>>(we, be, bp, Wq, bq, Wk, bk, Wv, bv, Wo, bo);
    spec_main<<<(N2 + 255) / 256, 256>>>(x, out, N2);
}

// round 10
// speedup vs baseline: 1.4025x; 1.2542x over previous
#include <cuda_runtime.h>
#include <cuda_fp16.h>
#include <cstdint>

#define NB 12
#define DM 128
#define NH 2
#define HD 64

struct Consts {
    float ta[NH];
    float u[NH];
    float bo;
    float pad[3];
    float tb[NH][NB];
    float gam[NH][NB];
    float w[NH][NB];
    float del[NH][NB][NB];
};

__device__ __align__(16) Consts g_c;
__device__ float g_av[3][DM];
__device__ float g_cv[3][NB][DM];

__device__ __forceinline__ __half2 h2ex2(__half2 v) {
    uint32_t a = *reinterpret_cast<uint32_t*>(&v), b;
    asm("ex2.approx.f16x2 %0, %1;" : "=r"(b) : "r"(a));
    return *reinterpret_cast<__half2*>(&b);
}
__device__ __forceinline__ float warp_sum(float v) {
    v += __shfl_xor_sync(0xffffffffu, v, 16);
    v += __shfl_xor_sync(0xffffffffu, v, 8);
    v += __shfl_xor_sync(0xffffffffu, v, 4);
    v += __shfl_xor_sync(0xffffffffu, v, 2);
    v += __shfl_xor_sync(0xffffffffu, v, 1);
    return v;
}

// ---------------------------------------------------------------------------
// Setup 1: one WARP per length-128 dot product (4992 warps). [round-6 proven]
// ---------------------------------------------------------------------------
__global__ __launch_bounds__(128) void spec_setup1(
        const float* __restrict__ we, const float* __restrict__ be,
        const float* __restrict__ bp,
        const float* __restrict__ Wq, const float* __restrict__ bq,
        const float* __restrict__ Wk, const float* __restrict__ bk,
        const float* __restrict__ Wv, const float* __restrict__ bv) {
    int gw = (blockIdx.x * blockDim.x + threadIdx.x) >> 5;
    int lane = threadIdx.x & 31;
    if (gw >= 3 * 13 * DM) return;
    int m = gw / (13 * DM);
    int r = gw % (13 * DM);
    int v = r / DM;
    int i = r % DM;
    const float* W  = (m == 0) ? Wq : (m == 1) ? Wk : Wv;
    const float* bb = (m == 0) ? bq : (m == 1) ? bk : bv;

    float4 rw = ((const float4*)(W + i * DM))[lane];
    float partial;
    if (v == 0) {
        float4 e = ((const float4*)we)[lane];
        partial = rw.x * e.x + rw.y * e.y + rw.z * e.z + rw.w * e.w;
    } else {
        float4 e = ((const float4*)be)[lane];
        float4 p = ((const float4*)(bp + (v - 1) * DM))[lane];
        partial = rw.x * (e.x + p.x) + rw.y * (e.y + p.y)
                + rw.z * (e.z + p.z) + rw.w * (e.w + p.w);
    }
    float s = warp_sum(partial);
    if (lane == 0) {
        if (v == 0) g_av[m][i] = s;
        else        g_cv[m][v - 1][i] = s + bb[i];
    }
}

// ---------------------------------------------------------------------------
// Setup 2: one WARP per length-64 dot product (365 warps). [round-6 proven]
// ---------------------------------------------------------------------------
__global__ __launch_bounds__(256) void spec_setup2(const float* __restrict__ Wo,
                                                   const float* __restrict__ bo) {
    int gw = (blockIdx.x * blockDim.x + threadIdx.x) >> 5;
    int lane = threadIdx.x & 31;
    const float cfac = 0.125f * 1.4426950408889634f;

    if (gw >= NH * 182) {
        if (gw == NH * 182 && lane == 0) g_c.bo = bo[0];
        return;
    }
    int h = gw / 182;
    int t = gw % 182;
    int off = h * HD;

    const float* a; const float* b; float* dst; float sc = cfac;
    if (t == 0)       { a = &g_av[0][off]; b = &g_av[1][off]; dst = &g_c.ta[h]; }
    else if (t == 1)  { a = &g_av[2][off]; b = Wo + off; dst = &g_c.u[h]; sc = 1.0f; }
    else if (t < 14)  { int bd = t - 2;  a = &g_av[0][off]; b = &g_cv[1][bd][off]; dst = &g_c.tb[h][bd]; }
    else if (t < 26)  { int bd = t - 14; a = &g_cv[0][bd][off]; b = &g_av[1][off]; dst = &g_c.gam[h][bd]; }
    else if (t < 38)  { int bd = t - 26; a = &g_cv[2][bd][off]; b = Wo + off; dst = &g_c.w[h][bd]; sc = 1.0f; }
    else {
        int idx = t - 38, q = idx / NB, k = idx % NB;
        a = &g_cv[0][q][off]; b = &g_cv[1][k][off]; dst = &g_c.del[h][q][k];
    }
    float2 av = ((const float2*)a)[lane];
    float2 bv = ((const float2*)b)[lane];
    float s = warp_sum(av.x * bv.x + av.y * bv.y);
    if (lane == 0) *dst = s * sc;
}

// ---------------------------------------------------------------------------
// Main kernel: 2 threads/token (one per head), fp16x2 over k-pairs.
// Register-slimmed (<=64 regs target): no fp32 xv copy (x reloaded in the
// epilogue), no precomputed xq2 array; 4 independent accumulation chains.
// ---------------------------------------------------------------------------
__global__ void __launch_bounds__(256, 4) spec_main(const float* __restrict__ x,
                                                    float* __restrict__ out, int N2) {
    __shared__ __half2 sDel[NH][NB][8];
    __shared__ __half2 sTb[NH][6], sW[NH][6];
    __shared__ __half2 sGam[NH][NB];
    __shared__ __half2 sTa[NH], sU[NH];
    __shared__ float sBo;

    {
        int td = threadIdx.x;
        for (int i = td; i < NH * NB * 6; i += 256) {
            int hh = i / (NB * 6);
            int r = i % (NB * 6);
            int q = r / 6, j = r % 6;
            sDel[hh][q][j] = __floats2half2_rn(g_c.del[hh][q][2 * j],
                                               g_c.del[hh][q][2 * j + 1]);
        }
        if (td < NH * 6) {
            int hh = td / 6, j = td % 6;
            sTb[hh][j] = __floats2half2_rn(g_c.tb[hh][2 * j], g_c.tb[hh][2 * j + 1]);
            sW[hh][j]  = __floats2half2_rn(g_c.w[hh][2 * j],  g_c.w[hh][2 * j + 1]);
        }
        if (td < NH * NB) {
            int hh = td / NB, q = td % NB;
            float g = g_c.gam[hh][q];
            sGam[hh][q] = __floats2half2_rn(g, g);
        }
        if (td < NH) {
            sTa[td] = __floats2half2_rn(g_c.ta[td], g_c.ta[td]);
            sU[td]  = __floats2half2_rn(g_c.u[td],  g_c.u[td]);
        }
        if (td == 0) sBo = g_c.bo;
    }
    __syncthreads();

    int t = blockIdx.x * blockDim.x + threadIdx.x;
    if (t >= N2) return;
    int n = t >> 1;
    int h = t & 1;

    // load x once, convert to packed half2 pairs; fp32 copy NOT kept
    __half2 x2[6];
    {
        const float4* xp = (const float4*)(x + (size_t)n * NB);
        float4 a0 = xp[0], a1 = xp[1], a2 = xp[2];
        x2[0] = __floats2half2_rn(a0.x, a0.y);
        x2[1] = __floats2half2_rn(a0.z, a0.w);
        x2[2] = __floats2half2_rn(a1.x, a1.y);
        x2[3] = __floats2half2_rn(a1.z, a1.w);
        x2[4] = __floats2half2_rn(a2.x, a2.y);
        x2[5] = __floats2half2_rn(a2.z, a2.w);
    }

    __half2 ah2 = sTa[h], uh2 = sU[h];
    __half2 t2[6], m2[6];
    #pragma unroll
    for (int j = 0; j < 6; j++) {
        t2[j] = __hfma2(x2[j], ah2, sTb[h][j]);
        m2[j] = __hfma2(x2[j], uh2, sW[h][j]);
    }

    float contrib[NB];
    #pragma unroll
    for (int q = 0; q < NB; q++) {
        __half2 gq2 = sGam[h][q];
        __half2 xq = ((q & 1) == 0) ? __low2half2(x2[q >> 1])
                                    : __high2half2(x2[q >> 1]);
        // 4 independent accumulation chains
        __half2 z = __floats2half2_rn(0.f, 0.f);
        __half2 rsA = z, rsB = z, dsA = z, dsB = z;
        #pragma unroll
        for (int j = 0; j < 3; j++) {
            __half2 sA = __hfma2(xq, t2[j],     __hfma2(x2[j],     gq2, sDel[h][q][j]));
            __half2 sB = __hfma2(xq, t2[j + 3], __hfma2(x2[j + 3], gq2, sDel[h][q][j + 3]));
            __half2 eA = h2ex2(sA);
            __half2 eB = h2ex2(sB);
            rsA = __hadd2(rsA, eA);
            rsB = __hadd2(rsB, eB);
            dsA = __hfma2(eA, m2[j], dsA);
            dsB = __hfma2(eB, m2[j + 3], dsB);
        }
        __half2 rs2 = __hadd2(rsA, rsB);
        __half2 ds2 = __hadd2(dsA, dsB);
        float2 rf = __half22float2(rs2);
        float2 df = __half22float2(ds2);
        contrib[q] = __fdividef(df.x + df.y, rf.x + rf.y);
    }

    #pragma unroll
    for (int q = 0; q < NB; q++)
        contrib[q] += __shfl_xor_sync(0xffffffffu, contrib[q], 1);

    if (h == 0) {
        float b = sBo;
        const float4* xp = (const float4*)(x + (size_t)n * NB);   // L1/L2 hit
        float4 a0 = xp[0], a1 = xp[1], a2 = xp[2];
        float4 o0 = make_float4(a0.x + contrib[0] + b,  a0.y + contrib[1] + b,
                                a0.z + contrib[2] + b,  a0.w + contrib[3] + b);
        float4 o1 = make_float4(a1.x + contrib[4] + b,  a1.y + contrib[5] + b,
                                a1.z + contrib[6] + b,  a1.w + contrib[7] + b);
        float4 o2 = make_float4(a2.x + contrib[8] + b,  a2.y + contrib[9] + b,
                                a2.z + contrib[10] + b, a2.w + contrib[11] + b);
        float4* op = (float4*)(out + (size_t)n * NB);
        op[0] = o0; op[1] = o1; op[2] = o2;
    }
}

// ---------------------------------------------------------------------------
extern "C" void kernel_launch(void* const* d_in, const int* in_sizes, int n_in,
                              void* d_out, int out_size) {
    const float* x  = (const float*)d_in[0];
    const float* we = (const float*)d_in[1];
    const float* be = (const float*)d_in[2];
    const float* bp = (const float*)d_in[3];
    const float* Wq = (const float*)d_in[4];
    const float* bq = (const float*)d_in[5];
    const float* Wk = (const float*)d_in[6];
    const float* bk = (const float*)d_in[7];
    const float* Wv = (const float*)d_in[8];
    const float* bv = (const float*)d_in[9];
    const float* Wo = (const float*)d_in[10];
    const float* bo = (const float*)d_in[11];
    float* out = (float*)d_out;

    int N = in_sizes[0] / NB;   // 65536 tokens
    int N2 = 2 * N;

    int s1_warps = 3 * 13 * DM;                 // 4992 warps
    spec_setup1<<<(s1_warps + 3) / 4, 128>>>(we, be, bp, Wq, bq, Wk, bk, Wv, bv);

    int s2_warps = NH * 182 + 1;                // 365 warps
    spec_setup2<<<(s2_warps + 7) / 8, 256>>>(Wo, bo);

    spec_main<<<(N2 + 255) / 256, 256>>>(x, out, N2);
}